// round 9
// baseline (speedup 1.0000x reference)
#include <cuda_runtime.h>
#include <cuda_bf16.h>
#include <cstdint>
#include <cstddef>

#define SEQ   2048
#define EMB   1024
#define HID   1024
#define VOC   50257
#define GATES 4096
#define NCTA  128

// ---------------- device scratch (static) ----------------
__device__ __nv_bfloat16 g_x[SEQ * EMB];
__device__ __nv_bfloat16 g_Wih[GATES * EMB];
__device__ __nv_bfloat16 g_Wout[(size_t)VOC * HID];
__device__ __nv_bfloat16 g_hs[SEQ * HID];
__device__ float         g_xgates[SEQ * GATES];
__device__ float         g_bias4[GATES];

// h-publication line: 8 h floats + flag in ONE 64B line, double-buffered.
struct __align__(64) HLine { float h[8]; unsigned flag; unsigned pad[6]; };
__device__ HLine g_hb[2][NCTA];

// ---------------- prep kernels ----------------
__global__ void k_init2(const float* __restrict__ bih, const float* __restrict__ bhh) {
    int i = blockIdx.x * blockDim.x + threadIdx.x;
    if (i < 2 * NCTA) g_hb[i >> 7][i & 127].flag = 0u;
    if (i < GATES) g_bias4[i] = bih[i] + bhh[i];
}

__global__ void k_prep(const int* __restrict__ seq, const float* __restrict__ emb,
                       const float* __restrict__ Wih) {
    int blk = blockIdx.x;
    if (blk < SEQ) {
        const float4* s = (const float4*)(emb + (size_t)seq[blk] * EMB);
        float4 v = s[threadIdx.x];
        __nv_bfloat162* d = (__nv_bfloat162*)(g_x + (size_t)blk * EMB);
        d[2 * threadIdx.x]     = __floats2bfloat162_rn(v.x, v.y);
        d[2 * threadIdx.x + 1] = __floats2bfloat162_rn(v.z, v.w);
    } else {
        size_t i = (size_t)(blk - SEQ) * blockDim.x + threadIdx.x;
        float4 v = ((const float4*)Wih)[i];
        __nv_bfloat162* d2 = (__nv_bfloat162*)g_Wih;
        d2[2 * i]     = __floats2bfloat162_rn(v.x, v.y);
        d2[2 * i + 1] = __floats2bfloat162_rn(v.z, v.w);
    }
}

__global__ void k_conv(const float* __restrict__ src, __nv_bfloat16* __restrict__ dst, size_t n4) {
    size_t i = (size_t)blockIdx.x * blockDim.x + threadIdx.x;
    if (i < n4) {
        float4 v = ((const float4*)src)[i];
        __nv_bfloat162* d2 = (__nv_bfloat162*)dst;
        d2[2*i]   = __floats2bfloat162_rn(v.x, v.y);
        d2[2*i+1] = __floats2bfloat162_rn(v.z, v.w);
    }
}

// ---------------- bf16 GEMM: C[M,N] = A[M,K] @ B[N,K]^T + bias ----------------
#define BM 128
#define BN 128
#define BK 32
#define SPAD 8

__device__ __forceinline__ void cp_async16(void* sd, const void* gs, int nbytes) {
    uint32_t s = (uint32_t)__cvta_generic_to_shared(sd);
    asm volatile("cp.async.cg.shared.global [%0], [%1], 16, %2;\n" :: "r"(s), "l"(gs), "r"(nbytes));
}
#define CP_COMMIT() asm volatile("cp.async.commit_group;\n" ::: "memory")
#define CP_WAIT(n)  asm volatile("cp.async.wait_group %0;\n" :: "n"(n) : "memory")

__device__ __forceinline__ void ldmx4(uint32_t* r, const void* p) {
    uint32_t a = (uint32_t)__cvta_generic_to_shared(p);
    asm volatile("ldmatrix.sync.aligned.m8n8.x4.shared.b16 {%0,%1,%2,%3}, [%4];\n"
                 : "=r"(r[0]), "=r"(r[1]), "=r"(r[2]), "=r"(r[3]) : "r"(a));
}
__device__ __forceinline__ void ldmx2(uint32_t* r, const void* p) {
    uint32_t a = (uint32_t)__cvta_generic_to_shared(p);
    asm volatile("ldmatrix.sync.aligned.m8n8.x2.shared.b16 {%0,%1}, [%2];\n"
                 : "=r"(r[0]), "=r"(r[1]) : "r"(a));
}
__device__ __forceinline__ void mma16816(float* c, const uint32_t* a, const uint32_t* b) {
    asm volatile("mma.sync.aligned.m16n8k16.row.col.f32.bf16.bf16.f32 "
                 "{%0,%1,%2,%3}, {%4,%5,%6,%7}, {%8,%9}, {%0,%1,%2,%3};\n"
                 : "+f"(c[0]), "+f"(c[1]), "+f"(c[2]), "+f"(c[3])
                 : "r"(a[0]), "r"(a[1]), "r"(a[2]), "r"(a[3]), "r"(b[0]), "r"(b[1]));
}

__global__ void __launch_bounds__(256) gemm_bf16(
    const __nv_bfloat16* __restrict__ A, const __nv_bfloat16* __restrict__ B,
    const float* __restrict__ bias, float* __restrict__ C, int N, int K)
{
    __shared__ __nv_bfloat16 As[2][BM][BK + SPAD];
    __shared__ __nv_bfloat16 Bs[2][BN][BK + SPAD];
    const int tid = threadIdx.x, warp = tid >> 5, lane = tid & 31;
    const int wm = warp >> 2, wn = warp & 3;
    const int m0 = blockIdx.y * BM, n0 = blockIdx.x * BN;

    float acc[4][4][4];
    #pragma unroll
    for (int i = 0; i < 4; i++)
        #pragma unroll
        for (int j = 0; j < 4; j++)
            #pragma unroll
            for (int q = 0; q < 4; q++) acc[i][j][q] = 0.f;

    const int ld_row = tid >> 1, ld_c = (tid & 1) * 2;

    auto stage_load = [&](int s, int kt) {
        const int kb = kt * BK;
        const __nv_bfloat16* ag = A + (size_t)(m0 + ld_row) * K + kb + ld_c * 8;
        cp_async16(&As[s][ld_row][ld_c * 8], ag, 16);
        cp_async16(&As[s][ld_row][(ld_c + 1) * 8], ag + 8, 16);
        int brow = n0 + ld_row;
        int ok = (brow < N) ? 16 : 0;
        int cr = (brow < N) ? brow : 0;
        const __nv_bfloat16* bg = B + (size_t)cr * K + kb + ld_c * 8;
        cp_async16(&Bs[s][ld_row][ld_c * 8], bg, ok);
        cp_async16(&Bs[s][ld_row][(ld_c + 1) * 8], bg + 8, ok);
    };

    const int NK = K / BK;
    stage_load(0, 0);
    CP_COMMIT();

    for (int kt = 0; kt < NK; kt++) {
        if (kt + 1 < NK) { stage_load((kt + 1) & 1, kt + 1); CP_COMMIT(); CP_WAIT(1); }
        else            { CP_WAIT(0); }
        __syncthreads();
        const int s = kt & 1;
        #pragma unroll
        for (int ks = 0; ks < 2; ks++) {
            uint32_t af[4][4], bf[4][2];
            #pragma unroll
            for (int mt = 0; mt < 4; mt++)
                ldmx4(af[mt], &As[s][wm*64 + mt*16 + (lane & 15)][ks*16 + (lane >> 4) * 8]);
            #pragma unroll
            for (int nt = 0; nt < 4; nt++)
                ldmx2(bf[nt], &Bs[s][wn*32 + nt*8 + (lane & 7)][ks*16 + ((lane >> 3) & 1) * 8]);
            #pragma unroll
            for (int mt = 0; mt < 4; mt++)
                #pragma unroll
                for (int nt = 0; nt < 4; nt++)
                    mma16816(acc[mt][nt], af[mt], bf[nt]);
        }
        __syncthreads();
    }

    #pragma unroll
    for (int mt = 0; mt < 4; mt++) {
        int r0 = m0 + wm*64 + mt*16 + (lane >> 2);
        #pragma unroll
        for (int nt = 0; nt < 4; nt++) {
            int c0 = n0 + wn*32 + nt*8 + (lane & 3) * 2;
            if (c0 < N) {
                float b0 = bias[c0];
                C[(size_t)r0 * N + c0]     = acc[mt][nt][0] + b0;
                C[(size_t)(r0+8) * N + c0] = acc[mt][nt][2] + b0;
            }
            if (c0 + 1 < N) {
                float b1 = bias[c0 + 1];
                C[(size_t)r0 * N + c0+1]     = acc[mt][nt][1] + b1;
                C[(size_t)(r0+8) * N + c0+1] = acc[mt][nt][3] + b1;
            }
        }
    }
}

// ---------------- persistent LSTM ----------------
__device__ __forceinline__ unsigned ld_cg_u32(const unsigned* p) {
    unsigned v;
    asm volatile("ld.global.cg.u32 %0, [%1];" : "=r"(v) : "l"(p) : "memory");
    return v;
}
__device__ __forceinline__ float4 ld_cg_f4(const float4* p) {
    float4 v;
    asm volatile("ld.global.cg.v4.f32 {%0,%1,%2,%3}, [%4];"
                 : "=f"(v.x), "=f"(v.y), "=f"(v.z), "=f"(v.w) : "l"(p) : "memory");
    return v;
}
__device__ __forceinline__ void st_cg_f32(float* p, float v) {
    asm volatile("st.global.cg.f32 [%0], %1;" :: "l"(p), "f"(v) : "memory");
}
__device__ __forceinline__ void st_release_u32(unsigned* p, unsigned v) {
    asm volatile("st.release.gpu.global.u32 [%0], %1;" :: "l"(p), "r"(v) : "memory");
}
__device__ __forceinline__ float tanh_approx(float x) {
    float y;
    asm("tanh.approx.f32 %0, %1;" : "=f"(y) : "f"(x));
    return y;
}

// 128 co-resident CTAs x 256 threads (round-7 proven FMA core).
// CTA b owns hidden units [8b,8b+8) -> 32 gate rows (lane l = gate row);
// warp w = 128-wide k-segment; weights in registers as float4.
// Exchange: HLine (8 h + flag, 64B, double-buffered). Warp 0 computes gates
// and publishes (st.cg h; syncwarp; st.release flag). Warps 4-7 concurrently
// poll the other CTAs' flags and pull h straight into smem (poll+fetch merged
// into one L2 round trip). 2 syncthreads per step.
__global__ void __launch_bounds__(256, 1) k_lstm(const float* __restrict__ Whh) {
    const int b = blockIdx.x, tid = threadIdx.x;
    const int w = tid >> 5, l = tid & 31;
    const int gate = l >> 3, u = l & 7;
    const int row = gate * HID + b * 8 + u;   // gate order i,f,g,o
    const int k0 = w * 128;

    float4 wreg[32];
    {
        const float4* wp = (const float4*)(Whh + (size_t)row * HID + k0);
        #pragma unroll
        for (int i = 0; i < 32; i++) wreg[i] = wp[i];
    }

    __shared__ __align__(16) float sh_h[HID];
    __shared__ float sm_part[8][32];
    float c_state = 0.f;  // valid on warp 0 lanes 0..7

    float xg_cur = (w == 0) ? __ldcg(&g_xgates[row]) : 0.f;

    #pragma unroll 1
    for (int t = 0; t < SEQ; t++) {
        float xg_next = 0.f;
        if (w == 0 && t + 1 < SEQ)
            xg_next = __ldcg(&g_xgates[(t + 1) * GATES + row]);

        // ---- FMA phase: 128 MACs per thread (reads sh_h written last step) ----
        float a0 = 0.f, a1 = 0.f, a2 = 0.f, a3 = 0.f;
        if (t > 0) {
            const float4* hp = (const float4*)&sh_h[k0];
            #pragma unroll
            for (int s = 0; s < 32; s++) {
                float4 h4 = hp[s];
                a0 = fmaf(wreg[s].x, h4.x, a0);
                a1 = fmaf(wreg[s].y, h4.y, a1);
                a2 = fmaf(wreg[s].z, h4.z, a2);
                a3 = fmaf(wreg[s].w, h4.w, a3);
            }
        }
        sm_part[w][l] = (a0 + a1) + (a2 + a3);
        __syncthreads();

        // ---- gate phase (warp 0) overlapped with poll+fetch (warps 4-7) ----
        if (w == 0) {
            float g = xg_cur;
            #pragma unroll
            for (int ww = 0; ww < 8; ww++) g += sm_part[ww][l];
            float sg = __fdividef(1.f, 1.f + __expf(-g));
            float v  = (gate == 2) ? tanh_approx(g) : sg;
            float iv = __shfl_sync(0xffffffffu, v, u);
            float fv = __shfl_sync(0xffffffffu, v, 8 + u);
            float gv = __shfl_sync(0xffffffffu, v, 16 + u);
            float ov = __shfl_sync(0xffffffffu, v, 24 + u);
            if (l < 8) {
                c_state = fv * c_state + iv * gv;
                float h = ov * tanh_approx(c_state);
                sh_h[b * 8 + l] = h;                       // own h locally
                st_cg_f32(&g_hb[(t + 1) & 1][b].h[l], h);  // publish
                g_hs[t * HID + b * 8 + l] = __float2bfloat16(h);
            }
            __syncwarp();
            if (l == 0) st_release_u32(&g_hb[(t + 1) & 1][b].flag, (unsigned)(t + 1));
        } else if (w >= 4 && t < SEQ - 1) {
            const int src = tid - 128;                     // 0..127
            if (src != b) {
                const HLine* hl = &g_hb[(t + 1) & 1][src];
                const unsigned tgt = (unsigned)(t + 1);
                while (ld_cg_u32(&hl->flag) < tgt) {}
                float4 v0 = ld_cg_f4((const float4*)&hl->h[0]);
                float4 v1 = ld_cg_f4((const float4*)&hl->h[4]);
                *(float4*)&sh_h[src * 8]     = v0;
                *(float4*)&sh_h[src * 8 + 4] = v1;
            }
        }
        xg_cur = xg_next;
        __syncthreads();
    }
}

// ---------------- log_softmax ----------------
__global__ void __launch_bounds__(256) k_lsm(float* __restrict__ out) {
    float* row = out + (size_t)blockIdx.x * VOC;
    __shared__ float rbuf[8];
    __shared__ float sres;
    const int tid = threadIdx.x, wid = tid >> 5, lane = tid & 31;

    float mx = -1e30f;
    for (int i = tid; i < VOC; i += 256) mx = fmaxf(mx, row[i]);
    #pragma unroll
    for (int o = 16; o; o >>= 1) mx = fmaxf(mx, __shfl_xor_sync(0xffffffffu, mx, o));
    if (lane == 0) rbuf[wid] = mx;
    __syncthreads();
    if (tid == 0) {
        float m = rbuf[0];
        #pragma unroll
        for (int i = 1; i < 8; i++) m = fmaxf(m, rbuf[i]);
        sres = m;
    }
    __syncthreads();
    mx = sres;
    __syncthreads();

    float s = 0.f;
    for (int i = tid; i < VOC; i += 256) s += __expf(row[i] - mx);
    #pragma unroll
    for (int o = 16; o; o >>= 1) s += __shfl_xor_sync(0xffffffffu, s, o);
    if (lane == 0) rbuf[wid] = s;
    __syncthreads();
    if (tid == 0) {
        float t = 0.f;
        #pragma unroll
        for (int i = 0; i < 8; i++) t += rbuf[i];
        sres = mx + logf(t);
    }
    __syncthreads();
    float lse = sres;
    for (int i = tid; i < VOC; i += 256) row[i] = row[i] - lse;
}

// ---------------- launch ----------------
extern "C" void kernel_launch(void* const* d_in, const int* in_sizes, int n_in,
                              void* d_out, int out_size) {
    const int*   seq  = (const int*)  d_in[0];
    const float* emb  = (const float*)d_in[1];
    const float* Wih  = (const float*)d_in[2];
    const float* Whh  = (const float*)d_in[3];
    const float* bih  = (const float*)d_in[4];
    const float* bhh  = (const float*)d_in[5];
    const float* Wout = (const float*)d_in[6];
    const float* bout = (const float*)d_in[7];
    float* out = (float*)d_out;

    void *p_x, *p_wih, *p_wout, *p_hs, *p_xg, *p_b4;
    cudaGetSymbolAddress(&p_x,    g_x);
    cudaGetSymbolAddress(&p_wih,  g_Wih);
    cudaGetSymbolAddress(&p_wout, g_Wout);
    cudaGetSymbolAddress(&p_hs,   g_hs);
    cudaGetSymbolAddress(&p_xg,   g_xgates);
    cudaGetSymbolAddress(&p_b4,   g_bias4);

    const size_t n4_ih  = (size_t)GATES * EMB / 4;
    const size_t n4_out = (size_t)VOC * HID / 4;

    // k_lstm kept in the ncu capture slot (4th launch).
    k_init2<<<GATES / 256, 256>>>(bih, bhh);                       // 1
    k_prep<<<(unsigned)(SEQ + n4_ih / 256), 256>>>(seq, emb, Wih); // 2

    {   // 3: xgates = x @ W_ih^T + (b_ih + b_hh)
        dim3 grid(GATES / BN, SEQ / BM);
        gemm_bf16<<<grid, 256>>>((const __nv_bfloat16*)p_x, (const __nv_bfloat16*)p_wih,
                                 (const float*)p_b4, (float*)p_xg, GATES, EMB);
    }

    k_lstm<<<NCTA, 256>>>(Whh);                                    // 4  <- profile here

    k_conv<<<(unsigned)((n4_out + 255) / 256), 256>>>(Wout, (__nv_bfloat16*)p_wout, n4_out); // 5

    {   // 6: logits = hs @ W_out^T + b_out -> d_out
        dim3 grid((VOC + BN - 1) / BN, SEQ / BM);
        gemm_bf16<<<grid, 256>>>((const __nv_bfloat16*)p_hs, (const __nv_bfloat16*)p_wout,
                                 bout, out, VOC, HID);
    }

    k_lsm<<<SEQ, 256>>>(out);                                      // 7
}

// round 11
// speedup vs baseline: 1.4243x; 1.4243x over previous
#include <cuda_runtime.h>
#include <cuda_bf16.h>
#include <cstdint>
#include <cstddef>

#define SEQ   2048
#define EMB   1024
#define HID   1024
#define VOC   50257
#define GATES 4096
#define NCTA  128

// ---------------- device scratch (static) ----------------
__device__ __nv_bfloat16 g_x[SEQ * EMB];
__device__ __nv_bfloat16 g_Wih[GATES * EMB];
__device__ __nv_bfloat16 g_Wout[(size_t)VOC * HID];
__device__ __nv_bfloat16 g_hs[SEQ * HID];
__device__ float         g_xgates[SEQ * GATES];
__device__ float         g_bias4[GATES];
__device__ float         g_h[2][HID];     // double-buffered h
__device__ unsigned      g_flag[NCTA];    // monotonic step counters (packed)

// ---------------- prep kernels ----------------
__global__ void k_init2(const float* __restrict__ bih, const float* __restrict__ bhh) {
    int i = blockIdx.x * blockDim.x + threadIdx.x;
    if (i < NCTA) g_flag[i] = 0u;
    if (i < GATES) g_bias4[i] = bih[i] + bhh[i];
}

__global__ void k_prep(const int* __restrict__ seq, const float* __restrict__ emb,
                       const float* __restrict__ Wih) {
    int blk = blockIdx.x;
    if (blk < SEQ) {
        const float4* s = (const float4*)(emb + (size_t)seq[blk] * EMB);
        float4 v = s[threadIdx.x];
        __nv_bfloat162* d = (__nv_bfloat162*)(g_x + (size_t)blk * EMB);
        d[2 * threadIdx.x]     = __floats2bfloat162_rn(v.x, v.y);
        d[2 * threadIdx.x + 1] = __floats2bfloat162_rn(v.z, v.w);
    } else {
        size_t i = (size_t)(blk - SEQ) * blockDim.x + threadIdx.x;
        float4 v = ((const float4*)Wih)[i];
        __nv_bfloat162* d2 = (__nv_bfloat162*)g_Wih;
        d2[2 * i]     = __floats2bfloat162_rn(v.x, v.y);
        d2[2 * i + 1] = __floats2bfloat162_rn(v.z, v.w);
    }
}

__global__ void k_conv(const float* __restrict__ src, __nv_bfloat16* __restrict__ dst, size_t n4) {
    size_t i = (size_t)blockIdx.x * blockDim.x + threadIdx.x;
    if (i < n4) {
        float4 v = ((const float4*)src)[i];
        __nv_bfloat162* d2 = (__nv_bfloat162*)dst;
        d2[2*i]   = __floats2bfloat162_rn(v.x, v.y);
        d2[2*i+1] = __floats2bfloat162_rn(v.z, v.w);
    }
}

// ---------------- bf16 GEMM: C[M,N] = A[M,K] @ B[N,K]^T + bias ----------------
#define BM 128
#define BN 128
#define BK 32
#define SPAD 8

__device__ __forceinline__ void cp_async16(void* sd, const void* gs, int nbytes) {
    uint32_t s = (uint32_t)__cvta_generic_to_shared(sd);
    asm volatile("cp.async.cg.shared.global [%0], [%1], 16, %2;\n" :: "r"(s), "l"(gs), "r"(nbytes));
}
#define CP_COMMIT() asm volatile("cp.async.commit_group;\n" ::: "memory")
#define CP_WAIT(n)  asm volatile("cp.async.wait_group %0;\n" :: "n"(n) : "memory")

__device__ __forceinline__ void ldmx4(uint32_t* r, const void* p) {
    uint32_t a = (uint32_t)__cvta_generic_to_shared(p);
    asm volatile("ldmatrix.sync.aligned.m8n8.x4.shared.b16 {%0,%1,%2,%3}, [%4];\n"
                 : "=r"(r[0]), "=r"(r[1]), "=r"(r[2]), "=r"(r[3]) : "r"(a));
}
__device__ __forceinline__ void ldmx2(uint32_t* r, const void* p) {
    uint32_t a = (uint32_t)__cvta_generic_to_shared(p);
    asm volatile("ldmatrix.sync.aligned.m8n8.x2.shared.b16 {%0,%1}, [%2];\n"
                 : "=r"(r[0]), "=r"(r[1]) : "r"(a));
}
__device__ __forceinline__ void mma16816(float* c, const uint32_t* a, const uint32_t* b) {
    asm volatile("mma.sync.aligned.m16n8k16.row.col.f32.bf16.bf16.f32 "
                 "{%0,%1,%2,%3}, {%4,%5,%6,%7}, {%8,%9}, {%0,%1,%2,%3};\n"
                 : "+f"(c[0]), "+f"(c[1]), "+f"(c[2]), "+f"(c[3])
                 : "r"(a[0]), "r"(a[1]), "r"(a[2]), "r"(a[3]), "r"(b[0]), "r"(b[1]));
}

__global__ void __launch_bounds__(256) gemm_bf16(
    const __nv_bfloat16* __restrict__ A, const __nv_bfloat16* __restrict__ B,
    const float* __restrict__ bias, float* __restrict__ C, int N, int K)
{
    __shared__ __nv_bfloat16 As[2][BM][BK + SPAD];
    __shared__ __nv_bfloat16 Bs[2][BN][BK + SPAD];
    const int tid = threadIdx.x, warp = tid >> 5, lane = tid & 31;
    const int wm = warp >> 2, wn = warp & 3;
    const int m0 = blockIdx.y * BM, n0 = blockIdx.x * BN;

    float acc[4][4][4];
    #pragma unroll
    for (int i = 0; i < 4; i++)
        #pragma unroll
        for (int j = 0; j < 4; j++)
            #pragma unroll
            for (int q = 0; q < 4; q++) acc[i][j][q] = 0.f;

    const int ld_row = tid >> 1, ld_c = (tid & 1) * 2;

    auto stage_load = [&](int s, int kt) {
        const int kb = kt * BK;
        const __nv_bfloat16* ag = A + (size_t)(m0 + ld_row) * K + kb + ld_c * 8;
        cp_async16(&As[s][ld_row][ld_c * 8], ag, 16);
        cp_async16(&As[s][ld_row][(ld_c + 1) * 8], ag + 8, 16);
        int brow = n0 + ld_row;
        int ok = (brow < N) ? 16 : 0;
        int cr = (brow < N) ? brow : 0;
        const __nv_bfloat16* bg = B + (size_t)cr * K + kb + ld_c * 8;
        cp_async16(&Bs[s][ld_row][ld_c * 8], bg, ok);
        cp_async16(&Bs[s][ld_row][(ld_c + 1) * 8], bg + 8, ok);
    };

    const int NK = K / BK;
    stage_load(0, 0);
    CP_COMMIT();

    for (int kt = 0; kt < NK; kt++) {
        if (kt + 1 < NK) { stage_load((kt + 1) & 1, kt + 1); CP_COMMIT(); CP_WAIT(1); }
        else            { CP_WAIT(0); }
        __syncthreads();
        const int s = kt & 1;
        #pragma unroll
        for (int ks = 0; ks < 2; ks++) {
            uint32_t af[4][4], bf[4][2];
            #pragma unroll
            for (int mt = 0; mt < 4; mt++)
                ldmx4(af[mt], &As[s][wm*64 + mt*16 + (lane & 15)][ks*16 + (lane >> 4) * 8]);
            #pragma unroll
            for (int nt = 0; nt < 4; nt++)
                ldmx2(bf[nt], &Bs[s][wn*32 + nt*8 + (lane & 7)][ks*16 + ((lane >> 3) & 1) * 8]);
            #pragma unroll
            for (int mt = 0; mt < 4; mt++)
                #pragma unroll
                for (int nt = 0; nt < 4; nt++)
                    mma16816(acc[mt][nt], af[mt], bf[nt]);
        }
        __syncthreads();
    }

    #pragma unroll
    for (int mt = 0; mt < 4; mt++) {
        int r0 = m0 + wm*64 + mt*16 + (lane >> 2);
        #pragma unroll
        for (int nt = 0; nt < 4; nt++) {
            int c0 = n0 + wn*32 + nt*8 + (lane & 3) * 2;
            if (c0 < N) {
                float b0 = bias[c0];
                C[(size_t)r0 * N + c0]     = acc[mt][nt][0] + b0;
                C[(size_t)(r0+8) * N + c0] = acc[mt][nt][2] + b0;
            }
            if (c0 + 1 < N) {
                float b1 = bias[c0 + 1];
                C[(size_t)r0 * N + c0+1]     = acc[mt][nt][1] + b1;
                C[(size_t)(r0+8) * N + c0+1] = acc[mt][nt][3] + b1;
            }
        }
    }
}

// ---------------- persistent LSTM ----------------
__device__ __forceinline__ unsigned ld_cg_u32(const unsigned* p) {
    unsigned v;
    asm volatile("ld.global.cg.u32 %0, [%1];" : "=r"(v) : "l"(p) : "memory");
    return v;
}
__device__ __forceinline__ void st_cg_u32(unsigned* p, unsigned v) {
    asm volatile("st.global.cg.u32 [%0], %1;" :: "l"(p), "r"(v) : "memory");
}
__device__ __forceinline__ float4 ld_cg_f4(const float4* p) {
    float4 v;
    asm volatile("ld.global.cg.v4.f32 {%0,%1,%2,%3}, [%4];"
                 : "=f"(v.x), "=f"(v.y), "=f"(v.z), "=f"(v.w) : "l"(p) : "memory");
    return v;
}
__device__ __forceinline__ void st_cg_f32(float* p, float v) {
    asm volatile("st.global.cg.f32 [%0], %1;" :: "l"(p), "f"(v) : "memory");
}
__device__ __forceinline__ float tanh_approx(float x) {
    float y;
    asm("tanh.approx.f32 %0, %1;" : "=f"(y) : "f"(x));
    return y;
}

// 128 co-resident CTAs x 256 threads (r7 FMA core, r7 fencing protocol).
// Per step, bounded by exactly two __syncthreads (A, C):
//   FMA -> sm_part -> A -> { warp 0: gates + publish(h, fence, flag=t+1)
//                          | warps 4-7: thread i polls g_flag[i] (coalesced,
//                            4 lines total), fences, fetches CTA i's h slice
//                            into sh_h }                      -> C
// Poll+fetch overlap the gate phase; the separate loop-top h fetch and two
// barriers of r7 are gone.
__global__ void __launch_bounds__(256, 1) k_lstm(const float* __restrict__ Whh) {
    const int b = blockIdx.x, tid = threadIdx.x;
    const int w = tid >> 5, l = tid & 31;
    const int gate = l >> 3, u = l & 7;
    const int row = gate * HID + b * 8 + u;   // gate order i,f,g,o
    const int k0 = w * 128;

    float4 wreg[32];
    {
        const float4* wp = (const float4*)(Whh + (size_t)row * HID + k0);
        #pragma unroll
        for (int i = 0; i < 32; i++) wreg[i] = wp[i];
    }

    __shared__ __align__(16) float sh_h[HID];
    __shared__ float sm_part[8][32];
    float c_state = 0.f;  // valid on warp 0 lanes 0..7

    float xg_cur = (w == 0) ? __ldcg(&g_xgates[row]) : 0.f;

    #pragma unroll 1
    for (int t = 0; t < SEQ; t++) {
        float xg_next = 0.f;
        if (w == 0 && t + 1 < SEQ)
            xg_next = __ldcg(&g_xgates[(t + 1) * GATES + row]);

        // ---- FMA phase: reads sh_h filled during previous step's exchange ----
        float a0 = 0.f, a1 = 0.f, a2 = 0.f, a3 = 0.f;
        if (t > 0) {
            const float4* hp = (const float4*)&sh_h[k0];
            #pragma unroll
            for (int s = 0; s < 32; s++) {
                float4 h4 = hp[s];
                a0 = fmaf(wreg[s].x, h4.x, a0);
                a1 = fmaf(wreg[s].y, h4.y, a1);
                a2 = fmaf(wreg[s].z, h4.z, a2);
                a3 = fmaf(wreg[s].w, h4.w, a3);
            }
        }
        sm_part[w][l] = (a0 + a1) + (a2 + a3);
        __syncthreads();                               // A

        if (w == 0) {
            // ---- gate phase + publish (r7 protocol: st.cg, fence, flag) ----
            float g = xg_cur;
            #pragma unroll
            for (int ww = 0; ww < 8; ww++) g += sm_part[ww][l];
            float sg = __fdividef(1.f, 1.f + __expf(-g));
            float v  = (gate == 2) ? tanh_approx(g) : sg;
            float iv = __shfl_sync(0xffffffffu, v, u);
            float fv = __shfl_sync(0xffffffffu, v, 8 + u);
            float gv = __shfl_sync(0xffffffffu, v, 16 + u);
            float ov = __shfl_sync(0xffffffffu, v, 24 + u);
            if (l < 8) {
                c_state = fv * c_state + iv * gv;
                float h = ov * tanh_approx(c_state);
                st_cg_f32(&g_h[(t + 1) & 1][b * 8 + l], h);
                g_hs[t * HID + b * 8 + l] = __float2bfloat16(h);
                __threadfence();
            }
            __syncwarp();
            if (l == 0) st_cg_u32(&g_flag[b], (unsigned)(t + 1));
        } else if (w >= 4 && t < SEQ - 1) {
            // ---- poll + fetch, overlapped with gate phase ----
            const int i = tid - 128;                   // 0..127: source CTA
            const unsigned tgt = (unsigned)(t + 1);
            while (ld_cg_u32(&g_flag[i]) < tgt) {}
            __threadfence();
            const float* src = &g_h[(t + 1) & 1][i * 8];
            float4 v0 = ld_cg_f4((const float4*)src);
            float4 v1 = ld_cg_f4((const float4*)(src + 4));
            *(float4*)&sh_h[i * 8]     = v0;
            *(float4*)&sh_h[i * 8 + 4] = v1;
        }
        xg_cur = xg_next;
        __syncthreads();                               // C
    }
}

// ---------------- log_softmax ----------------
__global__ void __launch_bounds__(256) k_lsm(float* __restrict__ out) {
    float* row = out + (size_t)blockIdx.x * VOC;
    __shared__ float rbuf[8];
    __shared__ float sres;
    const int tid = threadIdx.x, wid = tid >> 5, lane = tid & 31;

    float mx = -1e30f;
    for (int i = tid; i < VOC; i += 256) mx = fmaxf(mx, row[i]);
    #pragma unroll
    for (int o = 16; o; o >>= 1) mx = fmaxf(mx, __shfl_xor_sync(0xffffffffu, mx, o));
    if (lane == 0) rbuf[wid] = mx;
    __syncthreads();
    if (tid == 0) {
        float m = rbuf[0];
        #pragma unroll
        for (int i = 1; i < 8; i++) m = fmaxf(m, rbuf[i]);
        sres = m;
    }
    __syncthreads();
    mx = sres;
    __syncthreads();

    float s = 0.f;
    for (int i = tid; i < VOC; i += 256) s += __expf(row[i] - mx);
    #pragma unroll
    for (int o = 16; o; o >>= 1) s += __shfl_xor_sync(0xffffffffu, s, o);
    if (lane == 0) rbuf[wid] = s;
    __syncthreads();
    if (tid == 0) {
        float t = 0.f;
        #pragma unroll
        for (int i = 0; i < 8; i++) t += rbuf[i];
        sres = mx + logf(t);
    }
    __syncthreads();
    float lse = sres;
    for (int i = tid; i < VOC; i += 256) row[i] = row[i] - lse;
}

// ---------------- launch ----------------
extern "C" void kernel_launch(void* const* d_in, const int* in_sizes, int n_in,
                              void* d_out, int out_size) {
    const int*   seq  = (const int*)  d_in[0];
    const float* emb  = (const float*)d_in[1];
    const float* Wih  = (const float*)d_in[2];
    const float* Whh  = (const float*)d_in[3];
    const float* bih  = (const float*)d_in[4];
    const float* bhh  = (const float*)d_in[5];
    const float* Wout = (const float*)d_in[6];
    const float* bout = (const float*)d_in[7];
    float* out = (float*)d_out;

    void *p_x, *p_wih, *p_wout, *p_hs, *p_xg, *p_b4;
    cudaGetSymbolAddress(&p_x,    g_x);
    cudaGetSymbolAddress(&p_wih,  g_Wih);
    cudaGetSymbolAddress(&p_wout, g_Wout);
    cudaGetSymbolAddress(&p_hs,   g_hs);
    cudaGetSymbolAddress(&p_xg,   g_xgates);
    cudaGetSymbolAddress(&p_b4,   g_bias4);

    const size_t n4_ih  = (size_t)GATES * EMB / 4;
    const size_t n4_out = (size_t)VOC * HID / 4;

    // k_lstm kept in the ncu capture slot (4th launch).
    k_init2<<<GATES / 256, 256>>>(bih, bhh);                       // 1
    k_prep<<<(unsigned)(SEQ + n4_ih / 256), 256>>>(seq, emb, Wih); // 2

    {   // 3: xgates = x @ W_ih^T + (b_ih + b_hh)
        dim3 grid(GATES / BN, SEQ / BM);
        gemm_bf16<<<grid, 256>>>((const __nv_bfloat16*)p_x, (const __nv_bfloat16*)p_wih,
                                 (const float*)p_b4, (float*)p_xg, GATES, EMB);
    }

    k_lstm<<<NCTA, 256>>>(Whh);                                    // 4  <- profile here

    k_conv<<<(unsigned)((n4_out + 255) / 256), 256>>>(Wout, (__nv_bfloat16*)p_wout, n4_out); // 5

    {   // 6: logits = hs @ W_out^T + b_out -> d_out
        dim3 grid((VOC + BN - 1) / BN, SEQ / BM);
        gemm_bf16<<<grid, 256>>>((const __nv_bfloat16*)p_hs, (const __nv_bfloat16*)p_wout,
                                 bout, out, VOC, HID);
    }

    k_lsm<<<SEQ, 256>>>(out);                                      // 7
}